// round 1
// baseline (speedup 1.0000x reference)
#include <cuda_runtime.h>
#include <math.h>

#define NN 50000
#define EE 800000
#define GG 256
#define NB_AGG 6250   /* ceil(NN/8)    */
#define NB1    49     /* ceil(NN/1024) */

// ---------------- device scratch (no allocations allowed) ----------------
__device__ float g_H[NN * 32];
__device__ float g_O[NN * 32];
__device__ float g_P[NN * 128];
__device__ float g_Q[NN * 128];
__device__ float g_Etab[4 * 128];
__device__ int   g_cnt[NN];
__device__ int   g_rowptr[NN + 1];
__device__ int   g_cursor[NN];
__device__ int   g_pack[EE];
__device__ int   g_bsum[64];
__device__ float g_bnpart[NB_AGG * 64];
__device__ float g_bnAB[64];
__device__ float g_pool[GG * 32];

// ---------------- setup kernels ----------------
__global__ void k_zero() {
    int i = blockIdx.x * blockDim.x + threadIdx.x;
    if (i < NN) g_cnt[i] = 0;
    if (i < GG * 32) g_pool[i] = 0.f;
}

__global__ void k_count(const int* __restrict__ ei) {
    int e = blockIdx.x * blockDim.x + threadIdx.x;
    if (e < EE) atomicAdd(&g_cnt[ei[EE + e]], 1);
}

__global__ void k_scan1() {
    __shared__ int s[1024];
    int t = threadIdx.x;
    int i = blockIdx.x * 1024 + t;
    int v = (i < NN) ? g_cnt[i] : 0;
    s[t] = v;
    __syncthreads();
    for (int off = 1; off < 1024; off <<= 1) {
        int x = (t >= off) ? s[t - off] : 0;
        __syncthreads();
        s[t] += x;
        __syncthreads();
    }
    if (i < NN) g_rowptr[i] = s[t] - v;   // exclusive
    if (t == 1023) g_bsum[blockIdx.x] = s[1023];
}

__global__ void k_scan2() {
    __shared__ int sb[64];
    int t = threadIdx.x;
    if (t < NB1) sb[t] = g_bsum[t];
    __syncthreads();
    if (t == 0) {
        int run = 0;
        for (int b = 0; b < NB1; b++) { int x = sb[b]; sb[b] = run; run += x; }
    }
    __syncthreads();
    if (t < NB1) g_bsum[t] = sb[t];
}

__global__ void k_scan3() {
    int i = blockIdx.x * blockDim.x + threadIdx.x;
    if (i < NN) {
        int v = g_rowptr[i] + g_bsum[i >> 10];
        g_rowptr[i] = v;
        g_cursor[i] = v;
    }
    if (i == 0) g_rowptr[NN] = EE;
}

__global__ void k_scatter(const int* __restrict__ ei, const int* __restrict__ eattr) {
    int e = blockIdx.x * blockDim.x + threadIdx.x;
    if (e >= EE) return;
    int src = ei[e];
    int dst = ei[EE + e];
    int at  = eattr[e];
    int pos = atomicAdd(&g_cursor[dst], 1);
    g_pack[pos] = src | (at << 16);
}

__global__ void k_hinit(const int* __restrict__ x, const float* __restrict__ node_emb) {
    int i = blockIdx.x * blockDim.x + threadIdx.x;
    if (i >= NN * 32) return;
    int n = i >> 5, f = i & 31;
    g_H[i] = node_emb[x[n] * 32 + f];
}

// ---------------- per-layer kernels ----------------
// Etab[a][t*32+o] = sum_f e32[a][f] * pre_w[l][t][64+f][o] + pre_b[l][t][o]
__global__ void k_etab(const float* __restrict__ edge_emb, const float* __restrict__ enc_w,
                       const float* __restrict__ enc_b, const float* __restrict__ pre_w,
                       const float* __restrict__ pre_b, int l) {
    __shared__ float e32[4 * 32];
    int j = threadIdx.x;                 // 128 threads
    {
        int a = j >> 5, f = j & 31;
        float acc = enc_b[l * 32 + f];
        for (int k = 0; k < 50; k++)
            acc += edge_emb[a * 50 + k] * enc_w[(l * 50 + k) * 32 + f];
        e32[a * 32 + f] = acc;
    }
    __syncthreads();
    int t = j >> 5, o = j & 31;
    for (int a = 0; a < 4; a++) {
        float acc = pre_b[(l * 4 + t) * 32 + o];
        for (int f = 0; f < 32; f++)
            acc += e32[a * 32 + f] * pre_w[((l * 4 + t) * 96 + 64 + f) * 32 + o];
        g_Etab[a * 128 + j] = acc;
    }
}

// P = h @ A, Q = h @ B  ([N,32]@[32,128] each). Block=128 thr, 32 nodes/block,
// weights live in registers, h broadcast from shared.
__global__ void __launch_bounds__(128) k_pq(const float* __restrict__ pre_w, int l) {
    __shared__ float sh[32 * 32];
    int tid = threadIdx.x;
    int t = tid >> 5, o = tid & 31;
    const float* base = pre_w + ((size_t)(l * 4 + t) * 96) * 32 + o;
    float wa[32], wb[32];
#pragma unroll
    for (int f = 0; f < 32; f++) {
        wa[f] = base[f * 32];
        wb[f] = base[(f + 32) * 32];
    }
    int n0 = blockIdx.x * 32;
    for (int idx = tid; idx < 1024; idx += 128) {
        int node = idx >> 5, f = idx & 31;
        int n = n0 + node;
        sh[idx] = (n < NN) ? g_H[n * 32 + f] : 0.f;
    }
    __syncthreads();
    for (int node = 0; node < 32; node++) {
        int n = n0 + node;
        if (n >= NN) break;
        float p = 0.f, q = 0.f;
#pragma unroll
        for (int f = 0; f < 32; f++) {
            float hv = sh[node * 32 + f];
            p += hv * wa[f];
            q += hv * wb[f];
        }
        g_P[(size_t)n * 128 + tid] = p;
        g_Q[(size_t)n * 128 + tid] = q;
    }
}

#define FMA8(acc, av, v0, v1)                                             \
    acc[0] += (av) * (v0).x; acc[1] += (av) * (v0).y;                     \
    acc[2] += (av) * (v0).z; acc[3] += (av) * (v0).w;                     \
    acc[4] += (av) * (v1).x; acc[5] += (av) * (v1).y;                     \
    acc[6] += (av) * (v1).z; acc[7] += (av) * (v1).w;

// One warp per node: CSR gather + stats + fused post-MLP + lin, block BN partials.
__global__ void __launch_bounds__(256) k_agg(
    const float* __restrict__ post_w, const float* __restrict__ post_b,
    const float* __restrict__ lin_w,  const float* __restrict__ lin_b,
    const float* __restrict__ adl_p,  int l) {
    __shared__ float4 sEt[4][32];
    __shared__ float  sO[8][32];
    int warp = threadIdx.x >> 5, lane = threadIdx.x & 31;
    int n = blockIdx.x * 8 + warp;
    if (threadIdx.x < 128) {
        int a = threadIdx.x >> 5, L2 = threadIdx.x & 31;
        sEt[a][L2] = ((const float4*)g_Etab)[a * 32 + L2];
    }
    __syncthreads();

    float acc = 0.f;
    bool valid = (n < NN);
    if (valid) {
        int start = g_rowptr[n], end = g_rowptr[n + 1];
        const float4* Qv = (const float4*)g_Q;
        float4 s  = make_float4(0.f, 0.f, 0.f, 0.f);
        float4 sq = make_float4(0.f, 0.f, 0.f, 0.f);
        float4 mn = make_float4(1e30f, 1e30f, 1e30f, 1e30f);
        float4 mx = make_float4(-1e30f, -1e30f, -1e30f, -1e30f);
        for (int i = start; i < end; i++) {
            int pk  = __ldg(&g_pack[i]);
            int src = pk & 0xFFFF;
            int at  = pk >> 16;
            float4 v = Qv[(size_t)src * 32 + lane];
            float4 e = sEt[at][lane];
            v.x += e.x; v.y += e.y; v.z += e.z; v.w += e.w;
            s.x += v.x; s.y += v.y; s.z += v.z; s.w += v.w;
            sq.x += v.x * v.x; sq.y += v.y * v.y; sq.z += v.z * v.z; sq.w += v.w * v.w;
            mn.x = fminf(mn.x, v.x); mn.y = fminf(mn.y, v.y);
            mn.z = fminf(mn.z, v.z); mn.w = fminf(mn.w, v.w);
            mx.x = fmaxf(mx.x, v.x); mx.y = fmaxf(mx.y, v.y);
            mx.z = fmaxf(mx.z, v.z); mx.w = fmaxf(mx.w, v.w);
        }
        int   deg  = end - start;
        float degf = (float)deg;
        float degc = fmaxf(degf, 1.f);
        float inv  = 1.f / degc;
        float4 p = ((const float4*)g_P)[(size_t)n * 32 + lane];

        float sa[4][4];  // [stat][comp]: mean, min, max, std
        {
            float pv[4] = {p.x, p.y, p.z, p.w};
            float sv[4] = {s.x, s.y, s.z, s.w};
            float qv[4] = {sq.x, sq.y, sq.z, sq.w};
            float mnv[4] = {mn.x, mn.y, mn.z, mn.w};
            float mxv[4] = {mx.x, mx.y, mx.z, mx.w};
#pragma unroll
            for (int i = 0; i < 4; i++) {
                float mean = (degf * pv[i] + sv[i]) * inv;
                float msq  = (degf * pv[i] * pv[i] + 2.f * pv[i] * sv[i] + qv[i]) * inv;
                float var  = fmaxf(msq - mean * mean, 0.f) + 1e-5f;
                sa[0][i] = mean;
                sa[1][i] = (deg > 0) ? pv[i] + mnv[i] : 0.f;
                sa[2][i] = (deg > 0) ? pv[i] + mxv[i] : 0.f;
                sa[3][i] = sqrtf(var);
            }
        }
        float adl  = __ldg(adl_p);
        float logd = logf(degc + 1.f);
        float amp  = logd / adl;
        float att  = adl / logd;

        int sfl = lane & 7;
        int t   = lane >> 3;
        float4 h4 = ((const float4*)g_H)[(size_t)n * 8 + sfl];
        float ha[4] = {h4.x, h4.y, h4.z, h4.w};

        const float* Wt = post_w + (size_t)(l * 4 + t) * 416 * 8;
        float pb[8] = {0}, pa[8] = {0}, pt[8] = {0}, ph[8] = {0};
#pragma unroll
        for (int i = 0; i < 4; i++) {
            int row = sfl * 4 + i;
            const float4* wr = (const float4*)(Wt + row * 8);
            float4 w0 = wr[0], w1 = wr[1];
            FMA8(ph, ha[i], w0, w1);
        }
#pragma unroll
        for (int st = 0; st < 4; st++) {
#pragma unroll
            for (int i = 0; i < 4; i++) {
                float av = sa[st][i];
                int r = 32 + st * 32 + sfl * 4 + i;
                const float4* w0p = (const float4*)(Wt + r * 8);
                const float4* w1p = (const float4*)(Wt + (r + 128) * 8);
                const float4* w2p = (const float4*)(Wt + (r + 256) * 8);
                float4 b0 = w0p[0], b1 = w0p[1];
                FMA8(pb, av, b0, b1);
                float4 a0 = w1p[0], a1 = w1p[1];
                FMA8(pa, av, a0, a1);
                float4 t0 = w2p[0], t1 = w2p[1];
                FMA8(pt, av, t0, t1);
            }
        }
        float tot[8];
#pragma unroll
        for (int j = 0; j < 8; j++)
            tot[j] = ph[j] + pb[j] + amp * pa[j] + att * pt[j];
#pragma unroll
        for (int off = 1; off < 8; off <<= 1)
#pragma unroll
            for (int j = 0; j < 8; j++)
                tot[j] += __shfl_xor_sync(0xffffffffu, tot[j], off);
        float opre = tot[sfl] + post_b[(l * 4 + t) * 8 + sfl];

        // lin: o32[lane] = sum_c opre(c) * lin_w[l][c][lane] + lin_b
        acc = lin_b[l * 32 + lane];
#pragma unroll
        for (int c = 0; c < 32; c++) {
            float v = __shfl_sync(0xffffffffu, opre, c);
            acc += v * lin_w[l * 1024 + c * 32 + lane];
        }
        g_O[(size_t)n * 32 + lane] = acc;
    }
    sO[warp][lane] = valid ? acc : 0.f;
    __syncthreads();
    if (warp == 0) {
        float ssum = 0.f, ssq = 0.f;
#pragma unroll
        for (int w = 0; w < 8; w++) {
            float v = sO[w][lane];
            ssum += v;
            ssq += v * v;
        }
        g_bnpart[blockIdx.x * 64 + lane]      = ssum;
        g_bnpart[blockIdx.x * 64 + 32 + lane] = ssq;
    }
}

__global__ void k_bnreduce(const float* __restrict__ bn_g, const float* __restrict__ bn_b, int l) {
    __shared__ float sred[1024];
    int tid = threadIdx.x;
    int c = tid & 63, r = tid >> 6;  // 16 rows x 64 cols
    float partial = 0.f;
    for (int b = r; b < NB_AGG; b += 16)
        partial += g_bnpart[b * 64 + c];
    sred[tid] = partial;
    __syncthreads();
    for (int step = 8; step >= 1; step >>= 1) {
        if (r < step) sred[tid] += sred[tid + step * 64];
        __syncthreads();
    }
    if (tid < 32) {
        float sum = sred[tid];
        float sq  = sred[32 + tid];
        float mu  = sum / (float)NN;
        float var = sq / (float)NN - mu * mu;
        float istd = rsqrtf(var + 1e-5f);
        float A = bn_g[l * 32 + tid] * istd;
        float B = bn_b[l * 32 + tid] - mu * A;
        g_bnAB[tid]      = A;
        g_bnAB[32 + tid] = B;
    }
}

__global__ void k_bnapply() {
    int i = blockIdx.x * blockDim.x + threadIdx.x;
    if (i >= NN * 32) return;
    int c = i & 31;
    g_H[i] = fmaxf(g_O[i] * g_bnAB[c] + g_bnAB[32 + c], 0.f);
}

// ---------------- readout ----------------
__global__ void k_pool(const int* __restrict__ batch) {
    int i = blockIdx.x * blockDim.x + threadIdx.x;
    if (i >= NN * 32) return;
    int n = i >> 5, c = i & 31;
    atomicAdd(&g_pool[batch[n] * 32 + c], g_H[i]);
}

__global__ void k_final(const float* __restrict__ w1, const float* __restrict__ b1,
                        const float* __restrict__ w2, const float* __restrict__ b2,
                        const float* __restrict__ w3, const float* __restrict__ b3,
                        float* __restrict__ out) {
    __shared__ float sg[32], s1[50], s2[25];
    int g = blockIdx.x, t = threadIdx.x;
    if (t < 32) sg[t] = g_pool[g * 32 + t];
    __syncthreads();
    if (t < 50) {
        float a = b1[t];
        for (int c = 0; c < 32; c++) a += sg[c] * w1[c * 50 + t];
        s1[t] = fmaxf(a, 0.f);
    }
    __syncthreads();
    if (t < 25) {
        float a = b2[t];
        for (int j = 0; j < 50; j++) a += s1[j] * w2[j * 25 + t];
        s2[t] = fmaxf(a, 0.f);
    }
    __syncthreads();
    if (t == 0) {
        float a = b3[0];
        for (int k = 0; k < 25; k++) a += s2[k] * w3[k];
        out[g] = a;
    }
}

// ---------------- launch ----------------
extern "C" void kernel_launch(void* const* d_in, const int* in_sizes, int n_in,
                              void* d_out, int out_size) {
    const int*   x        = (const int*)d_in[0];
    const int*   ei       = (const int*)d_in[1];
    const int*   eattr    = (const int*)d_in[2];
    const int*   batch    = (const int*)d_in[3];
    const float* node_emb = (const float*)d_in[4];
    const float* edge_emb = (const float*)d_in[5];
    const float* enc_w    = (const float*)d_in[6];
    const float* enc_b    = (const float*)d_in[7];
    const float* pre_w    = (const float*)d_in[8];
    const float* pre_b    = (const float*)d_in[9];
    const float* post_w   = (const float*)d_in[10];
    const float* post_b   = (const float*)d_in[11];
    const float* lin_w    = (const float*)d_in[12];
    const float* lin_b    = (const float*)d_in[13];
    const float* bn_g     = (const float*)d_in[14];
    const float* bn_b     = (const float*)d_in[15];
    const float* mlp_w1   = (const float*)d_in[16];
    const float* mlp_b1   = (const float*)d_in[17];
    const float* mlp_w2   = (const float*)d_in[18];
    const float* mlp_b2   = (const float*)d_in[19];
    const float* mlp_w3   = (const float*)d_in[20];
    const float* mlp_b3   = (const float*)d_in[21];
    const float* adl      = (const float*)d_in[22];
    float* out = (float*)d_out;

    int gN   = (NN + 255) / 256;
    int gE   = (EE + 255) / 256;
    int gN32 = (NN * 32 + 255) / 256;

    k_zero<<<gN, 256>>>();
    k_count<<<gE, 256>>>(ei);
    k_scan1<<<NB1, 1024>>>();
    k_scan2<<<1, 64>>>();
    k_scan3<<<gN, 256>>>();
    k_scatter<<<gE, 256>>>(ei, eattr);
    k_hinit<<<gN32, 256>>>(x, node_emb);

    for (int l = 0; l < 4; l++) {
        k_etab<<<1, 128>>>(edge_emb, enc_w, enc_b, pre_w, pre_b, l);
        k_pq<<<(NN + 31) / 32, 128>>>(pre_w, l);
        k_agg<<<NB_AGG, 256>>>(post_w, post_b, lin_w, lin_b, adl, l);
        k_bnreduce<<<1, 1024>>>(bn_g, bn_b, l);
        k_bnapply<<<gN32, 256>>>();
    }
    k_pool<<<gN32, 256>>>(batch);
    k_final<<<GG, 64>>>(mlp_w1, mlp_b1, mlp_w2, mlp_b2, mlp_w3, mlp_b3, out);
}

// round 2
// speedup vs baseline: 2.6748x; 2.6748x over previous
#include <cuda_runtime.h>
#include <math.h>

#define NN 50000
#define EE 800000
#define GG 256
#define NB_AGG 6250   /* ceil(NN/8)    */
#define NB1    49     /* ceil(NN/1024) */
#define NB_MLP 196    /* ceil(NN/256)  */

// ---------------- device scratch (no allocations allowed) ----------------
__device__ float g_H[NN * 32];
__device__ float g_O[NN * 32];
__device__ float g_P[NN * 128];
__device__ float g_Q[NN * 128];
__device__ float g_AGG[(size_t)NN * 512];
__device__ float g_Etab[4 * 128];
__device__ int   g_cnt[NN];
__device__ int   g_rowptr[NN + 1];
__device__ int   g_cursor[NN];
__device__ int   g_pack[EE];
__device__ int   g_bsum[64];
__device__ float g_bnacc[64];
__device__ float g_bnAB[64];
__device__ float g_pool[GG * 32];

// ---------------- setup kernels ----------------
__global__ void k_zero() {
    int i = blockIdx.x * blockDim.x + threadIdx.x;
    if (i < NN) g_cnt[i] = 0;
    if (i < GG * 32) g_pool[i] = 0.f;
    if (i < 64) g_bnacc[i] = 0.f;
}

__global__ void k_count(const int* __restrict__ ei) {
    int e = blockIdx.x * blockDim.x + threadIdx.x;
    if (e < EE) atomicAdd(&g_cnt[ei[EE + e]], 1);
}

__global__ void k_scan1() {
    __shared__ int s[1024];
    int t = threadIdx.x;
    int i = blockIdx.x * 1024 + t;
    int v = (i < NN) ? g_cnt[i] : 0;
    s[t] = v;
    __syncthreads();
    for (int off = 1; off < 1024; off <<= 1) {
        int x = (t >= off) ? s[t - off] : 0;
        __syncthreads();
        s[t] += x;
        __syncthreads();
    }
    if (i < NN) g_rowptr[i] = s[t] - v;   // exclusive
    if (t == 1023) g_bsum[blockIdx.x] = s[1023];
}

__global__ void k_scan2() {
    __shared__ int sb[64];
    int t = threadIdx.x;
    if (t < NB1) sb[t] = g_bsum[t];
    __syncthreads();
    if (t == 0) {
        int run = 0;
        for (int b = 0; b < NB1; b++) { int x = sb[b]; sb[b] = run; run += x; }
    }
    __syncthreads();
    if (t < NB1) g_bsum[t] = sb[t];
}

__global__ void k_scan3() {
    int i = blockIdx.x * blockDim.x + threadIdx.x;
    if (i < NN) {
        int v = g_rowptr[i] + g_bsum[i >> 10];
        g_rowptr[i] = v;
        g_cursor[i] = v;
    }
    if (i == 0) g_rowptr[NN] = EE;
}

__global__ void k_scatter(const int* __restrict__ ei, const int* __restrict__ eattr) {
    int e = blockIdx.x * blockDim.x + threadIdx.x;
    if (e >= EE) return;
    int src = ei[e];
    int dst = ei[EE + e];
    int at  = eattr[e];
    int pos = atomicAdd(&g_cursor[dst], 1);
    g_pack[pos] = src | (at << 16);
}

__global__ void k_hinit(const int* __restrict__ x, const float* __restrict__ node_emb) {
    int i = blockIdx.x * blockDim.x + threadIdx.x;
    if (i >= NN * 32) return;
    int n = i >> 5, f = i & 31;
    g_H[i] = node_emb[x[n] * 32 + f];
}

// ---------------- per-layer kernels ----------------
// Etab[a][t*32+o] = sum_f e32[a][f] * pre_w[l][t][64+f][o] + pre_b[l][t][o]
__global__ void k_etab(const float* __restrict__ edge_emb, const float* __restrict__ enc_w,
                       const float* __restrict__ enc_b, const float* __restrict__ pre_w,
                       const float* __restrict__ pre_b, int l) {
    __shared__ float e32[4 * 32];
    int j = threadIdx.x;                 // 128 threads
    {
        int a = j >> 5, f = j & 31;
        float acc = enc_b[l * 32 + f];
        for (int k = 0; k < 50; k++)
            acc += edge_emb[a * 50 + k] * enc_w[(l * 50 + k) * 32 + f];
        e32[a * 32 + f] = acc;
    }
    __syncthreads();
    int t = j >> 5, o = j & 31;
    for (int a = 0; a < 4; a++) {
        float acc = pre_b[(l * 4 + t) * 32 + o];
        for (int f = 0; f < 32; f++)
            acc += e32[a * 32 + f] * pre_w[((l * 4 + t) * 96 + 64 + f) * 32 + o];
        g_Etab[a * 128 + j] = acc;
    }
}

// P = h @ A, Q = h @ B  ([N,32]@[32,128] each).
__global__ void __launch_bounds__(128) k_pq(const float* __restrict__ pre_w, int l) {
    __shared__ float sh[32 * 32];
    int tid = threadIdx.x;
    int t = tid >> 5, o = tid & 31;
    const float* base = pre_w + ((size_t)(l * 4 + t) * 96) * 32 + o;
    float wa[32], wb[32];
#pragma unroll
    for (int f = 0; f < 32; f++) {
        wa[f] = base[f * 32];
        wb[f] = base[(f + 32) * 32];
    }
    int n0 = blockIdx.x * 32;
    for (int idx = tid; idx < 1024; idx += 128) {
        int node = idx >> 5, f = idx & 31;
        int n = n0 + node;
        sh[idx] = (n < NN) ? g_H[n * 32 + f] : 0.f;
    }
    __syncthreads();
    for (int node = 0; node < 32; node++) {
        int n = n0 + node;
        if (n >= NN) break;
        float p = 0.f, q = 0.f;
#pragma unroll
        for (int f = 0; f < 32; f++) {
            float hv = sh[node * 32 + f];
            p += hv * wa[f];
            q += hv * wb[f];
        }
        g_P[(size_t)n * 128 + tid] = p;
        g_Q[(size_t)n * 128 + tid] = q;
    }
}

#define ACC4(v)                                                          \
    s.x += (v).x; s.y += (v).y; s.z += (v).z; s.w += (v).w;              \
    sq.x += (v).x * (v).x; sq.y += (v).y * (v).y;                        \
    sq.z += (v).z * (v).z; sq.w += (v).w * (v).w;                        \
    mn.x = fminf(mn.x, (v).x); mn.y = fminf(mn.y, (v).y);                \
    mn.z = fminf(mn.z, (v).z); mn.w = fminf(mn.w, (v).w);                \
    mx.x = fmaxf(mx.x, (v).x); mx.y = fmaxf(mx.y, (v).y);                \
    mx.z = fmaxf(mx.z, (v).z); mx.w = fmaxf(mx.w, (v).w);

// One warp per node: CSR gather + PNA stats -> g_AGG[N][512]
__global__ void __launch_bounds__(256) k_stats() {
    __shared__ float4 sEt[4][32];
    int warp = threadIdx.x >> 5, lane = threadIdx.x & 31;
    int n = blockIdx.x * 8 + warp;
    if (threadIdx.x < 128) {
        int a = threadIdx.x >> 5, L2 = threadIdx.x & 31;
        sEt[a][L2] = ((const float4*)g_Etab)[a * 32 + L2];
    }
    __syncthreads();
    if (n >= NN) return;

    int start = g_rowptr[n], end = g_rowptr[n + 1];
    const float4* Qv = (const float4*)g_Q;
    float4 s  = make_float4(0.f, 0.f, 0.f, 0.f);
    float4 sq = make_float4(0.f, 0.f, 0.f, 0.f);
    float4 mn = make_float4(1e30f, 1e30f, 1e30f, 1e30f);
    float4 mx = make_float4(-1e30f, -1e30f, -1e30f, -1e30f);
    int i = start;
    for (; i + 4 <= end; i += 4) {
        int pk0 = __ldg(&g_pack[i]);
        int pk1 = __ldg(&g_pack[i + 1]);
        int pk2 = __ldg(&g_pack[i + 2]);
        int pk3 = __ldg(&g_pack[i + 3]);
        float4 v0 = Qv[(size_t)(pk0 & 0xFFFF) * 32 + lane];
        float4 v1 = Qv[(size_t)(pk1 & 0xFFFF) * 32 + lane];
        float4 v2 = Qv[(size_t)(pk2 & 0xFFFF) * 32 + lane];
        float4 v3 = Qv[(size_t)(pk3 & 0xFFFF) * 32 + lane];
        float4 e0 = sEt[pk0 >> 16][lane];
        float4 e1 = sEt[pk1 >> 16][lane];
        float4 e2 = sEt[pk2 >> 16][lane];
        float4 e3 = sEt[pk3 >> 16][lane];
        v0.x += e0.x; v0.y += e0.y; v0.z += e0.z; v0.w += e0.w;
        v1.x += e1.x; v1.y += e1.y; v1.z += e1.z; v1.w += e1.w;
        v2.x += e2.x; v2.y += e2.y; v2.z += e2.z; v2.w += e2.w;
        v3.x += e3.x; v3.y += e3.y; v3.z += e3.z; v3.w += e3.w;
        ACC4(v0) ACC4(v1) ACC4(v2) ACC4(v3)
    }
    for (; i < end; i++) {
        int pk = __ldg(&g_pack[i]);
        float4 v = Qv[(size_t)(pk & 0xFFFF) * 32 + lane];
        float4 e = sEt[pk >> 16][lane];
        v.x += e.x; v.y += e.y; v.z += e.z; v.w += e.w;
        ACC4(v)
    }
    int   deg  = end - start;
    float degf = (float)deg;
    float degc = fmaxf(degf, 1.f);
    float inv  = 1.f / degc;
    float4 p = ((const float4*)g_P)[(size_t)n * 32 + lane];

    float pv[4]  = {p.x, p.y, p.z, p.w};
    float sv[4]  = {s.x, s.y, s.z, s.w};
    float qv[4]  = {sq.x, sq.y, sq.z, sq.w};
    float mnv[4] = {mn.x, mn.y, mn.z, mn.w};
    float mxv[4] = {mx.x, mx.y, mx.z, mx.w};
    float4 st0, st1, st2, st3;
    float* o0 = (float*)&st0; float* o1 = (float*)&st1;
    float* o2 = (float*)&st2; float* o3 = (float*)&st3;
#pragma unroll
    for (int k = 0; k < 4; k++) {
        float mean = (degf * pv[k] + sv[k]) * inv;
        float msq  = (degf * pv[k] * pv[k] + 2.f * pv[k] * sv[k] + qv[k]) * inv;
        float var  = fmaxf(msq - mean * mean, 0.f) + 1e-5f;
        o0[k] = mean;
        o1[k] = (deg > 0) ? pv[k] + mnv[k] : 0.f;
        o2[k] = (deg > 0) ? pv[k] + mxv[k] : 0.f;
        o3[k] = sqrtf(var);
    }
    // AGG layout: [n][t*128 + st*32 + o], lane holds tower t=lane>>3, o=(lane&7)*4..+3
    size_t base = (size_t)n * 512 + (lane >> 3) * 128 + (lane & 7) * 4;
    *(float4*)&g_AGG[base]       = st0;
    *(float4*)&g_AGG[base + 32]  = st1;
    *(float4*)&g_AGG[base + 64]  = st2;
    *(float4*)&g_AGG[base + 96]  = st3;
}

#define FMA8(acc, av, v0, v1)                                             \
    acc[0] += (av) * (v0).x; acc[1] += (av) * (v0).y;                     \
    acc[2] += (av) * (v0).z; acc[3] += (av) * (v0).w;                     \
    acc[4] += (av) * (v1).x; acc[5] += (av) * (v1).y;                     \
    acc[6] += (av) * (v1).z; acc[7] += (av) * (v1).w;

// Thread per node: fused post-MLP (base/amp/att blocks) + lin. Weights in smem,
// all weight reads warp-uniform broadcasts.
__global__ void __launch_bounds__(256) k_mlp(
    const float* __restrict__ post_w, const float* __restrict__ post_b,
    const float* __restrict__ lin_w,  const float* __restrict__ lin_b,
    const float* __restrict__ adl_p,  int l) {
    __shared__ float sW[12288];   // [t][r(128)][m(3)][c(8)] = 48KB
    int tid = threadIdx.x;
    const float* pw = post_w + (size_t)l * 4 * 416 * 8;
    for (int idx = tid; idx < 12288; idx += 256) {
        int c  = idx & 7;
        int rm = idx >> 3;
        int m  = rm % 3;
        int tr = rm / 3;
        int r  = tr & 127;
        int t  = tr >> 7;
        sW[idx] = pw[((size_t)t * 416 + 32 + m * 128 + r) * 8 + c];
    }
    __syncthreads();
    int n = blockIdx.x * 256 + tid;
    if (n >= NN) return;

    int deg = g_rowptr[n + 1] - g_rowptr[n];
    float degc = fmaxf((float)deg, 1.f);
    float adl  = __ldg(adl_p);
    float logd = logf(degc + 1.f);
    float amp  = logd / adl;
    float att  = adl / logd;

    float o32[32];
#pragma unroll
    for (int t = 0; t < 4; t++)
#pragma unroll
        for (int c = 0; c < 8; c++)
            o32[t * 8 + c] = __ldg(&post_b[(l * 4 + t) * 8 + c]);

    // h part: rows 0..31 of each tower's post_w (uniform global reads, L1-hot)
    {
        const float* hrow = g_H + (size_t)n * 32;
#pragma unroll 8
        for (int f = 0; f < 32; f++) {
            float hv = __ldg(&hrow[f]);
#pragma unroll
            for (int t = 0; t < 4; t++) {
                const float4* wr = (const float4*)(pw + ((size_t)t * 416 + f) * 8);
                float4 w0 = __ldg(wr), w1 = __ldg(wr + 1);
                float* acc = &o32[t * 8];
                FMA8(acc, hv, w0, w1);
            }
        }
    }

    // agg part: per tower, 128 rows x 3 matrices from smem (broadcast)
#pragma unroll
    for (int t = 0; t < 4; t++) {
        float y1[8] = {0}, y2[8] = {0}, y3[8] = {0};
        const float* arow = g_AGG + (size_t)n * 512 + t * 128;
        for (int r = 0; r < 128; r += 4) {
            float4 av = __ldg((const float4*)(arow + r));
            float a[4] = {av.x, av.y, av.z, av.w};
#pragma unroll
            for (int rr = 0; rr < 4; rr++) {
                const float4* wb = (const float4*)&sW[(t * 128 + r + rr) * 24];
                float4 b0 = wb[0], b1 = wb[1];
                FMA8(y1, a[rr], b0, b1);
                float4 c0 = wb[2], c1 = wb[3];
                FMA8(y2, a[rr], c0, c1);
                float4 d0 = wb[4], d1 = wb[5];
                FMA8(y3, a[rr], d0, d1);
            }
        }
#pragma unroll
        for (int c = 0; c < 8; c++)
            o32[t * 8 + c] += y1[c] + amp * y2[c] + att * y3[c];
    }

    // lin: acc[j] = lin_b[j] + sum_c o32[c]*lin_w[c][j]  (uniform global reads)
    float acc[32];
    {
        const float* lb = lin_b + l * 32;
#pragma unroll
        for (int j = 0; j < 8; j++) {
            float4 b = __ldg((const float4*)(lb + j * 4));
            acc[j * 4] = b.x; acc[j * 4 + 1] = b.y; acc[j * 4 + 2] = b.z; acc[j * 4 + 3] = b.w;
        }
        const float* lw = lin_w + l * 1024;
#pragma unroll 8
        for (int c = 0; c < 32; c++) {
            float v = o32[c];
#pragma unroll
            for (int j = 0; j < 8; j++) {
                float4 w = __ldg((const float4*)(lw + c * 32 + j * 4));
                acc[j * 4]     += v * w.x;
                acc[j * 4 + 1] += v * w.y;
                acc[j * 4 + 2] += v * w.z;
                acc[j * 4 + 3] += v * w.w;
            }
        }
    }
    float* orow = g_O + (size_t)n * 32;
#pragma unroll
    for (int j = 0; j < 8; j++)
        ((float4*)orow)[j] = make_float4(acc[j * 4], acc[j * 4 + 1], acc[j * 4 + 2], acc[j * 4 + 3]);
}

// BN statistics: grid-stride over g_O, per-block smem reduce + atomicAdd
__global__ void __launch_bounds__(256) k_bnstats() {
    __shared__ float ss[256], sq2[256];
    int tid = threadIdx.x;
    float s = 0.f, q = 0.f;
    int stride = gridDim.x * 256;      // multiple of 32 -> channel fixed per thread
    for (int i = blockIdx.x * 256 + tid; i < NN * 32; i += stride) {
        float v = g_O[i];
        s += v;
        q += v * v;
    }
    ss[tid] = s; sq2[tid] = q;
    __syncthreads();
    if (tid < 32) {
        float as = 0.f, aq = 0.f;
#pragma unroll
        for (int k = 0; k < 8; k++) {
            as += ss[k * 32 + tid];
            aq += sq2[k * 32 + tid];
        }
        atomicAdd(&g_bnacc[tid], as);
        atomicAdd(&g_bnacc[32 + tid], aq);
    }
}

__global__ void k_bnfin(const float* __restrict__ bn_g, const float* __restrict__ bn_b, int l) {
    int tid = threadIdx.x;   // 32 threads
    float sum = g_bnacc[tid];
    float sq  = g_bnacc[32 + tid];
    float mu  = sum / (float)NN;
    float var = sq / (float)NN - mu * mu;
    float istd = rsqrtf(var + 1e-5f);
    float A = bn_g[l * 32 + tid] * istd;
    float B = bn_b[l * 32 + tid] - mu * A;
    g_bnAB[tid]      = A;
    g_bnAB[32 + tid] = B;
    g_bnacc[tid]      = 0.f;   // reset for next layer
    g_bnacc[32 + tid] = 0.f;
}

__global__ void k_bnapply() {
    int i = blockIdx.x * blockDim.x + threadIdx.x;
    if (i >= NN * 32) return;
    int c = i & 31;
    g_H[i] = fmaxf(g_O[i] * g_bnAB[c] + g_bnAB[32 + c], 0.f);
}

// ---------------- readout ----------------
__global__ void k_pool(const int* __restrict__ batch) {
    int i = blockIdx.x * blockDim.x + threadIdx.x;
    if (i >= NN * 32) return;
    int n = i >> 5, c = i & 31;
    atomicAdd(&g_pool[batch[n] * 32 + c], g_H[i]);
}

__global__ void k_final(const float* __restrict__ w1, const float* __restrict__ b1,
                        const float* __restrict__ w2, const float* __restrict__ b2,
                        const float* __restrict__ w3, const float* __restrict__ b3,
                        float* __restrict__ out) {
    __shared__ float sg[32], s1[50], s2[25];
    int g = blockIdx.x, t = threadIdx.x;
    if (t < 32) sg[t] = g_pool[g * 32 + t];
    __syncthreads();
    if (t < 50) {
        float a = b1[t];
        for (int c = 0; c < 32; c++) a += sg[c] * w1[c * 50 + t];
        s1[t] = fmaxf(a, 0.f);
    }
    __syncthreads();
    if (t < 25) {
        float a = b2[t];
        for (int j = 0; j < 50; j++) a += s1[j] * w2[j * 25 + t];
        s2[t] = fmaxf(a, 0.f);
    }
    __syncthreads();
    if (t == 0) {
        float a = b3[0];
        for (int k = 0; k < 25; k++) a += s2[k] * w3[k];
        out[g] = a;
    }
}

// ---------------- launch ----------------
extern "C" void kernel_launch(void* const* d_in, const int* in_sizes, int n_in,
                              void* d_out, int out_size) {
    const int*   x        = (const int*)d_in[0];
    const int*   ei       = (const int*)d_in[1];
    const int*   eattr    = (const int*)d_in[2];
    const int*   batch    = (const int*)d_in[3];
    const float* node_emb = (const float*)d_in[4];
    const float* edge_emb = (const float*)d_in[5];
    const float* enc_w    = (const float*)d_in[6];
    const float* enc_b    = (const float*)d_in[7];
    const float* pre_w    = (const float*)d_in[8];
    const float* pre_b    = (const float*)d_in[9];
    const float* post_w   = (const float*)d_in[10];
    const float* post_b   = (const float*)d_in[11];
    const float* lin_w    = (const float*)d_in[12];
    const float* lin_b    = (const float*)d_in[13];
    const float* bn_g     = (const float*)d_in[14];
    const float* bn_b     = (const float*)d_in[15];
    const float* mlp_w1   = (const float*)d_in[16];
    const float* mlp_b1   = (const float*)d_in[17];
    const float* mlp_w2   = (const float*)d_in[18];
    const float* mlp_b2   = (const float*)d_in[19];
    const float* mlp_w3   = (const float*)d_in[20];
    const float* mlp_b3   = (const float*)d_in[21];
    const float* adl      = (const float*)d_in[22];
    float* out = (float*)d_out;

    int gN   = (NN + 255) / 256;
    int gE   = (EE + 255) / 256;
    int gN32 = (NN * 32 + 255) / 256;

    k_zero<<<gN, 256>>>();
    k_count<<<gE, 256>>>(ei);
    k_scan1<<<NB1, 1024>>>();
    k_scan2<<<1, 64>>>();
    k_scan3<<<gN, 256>>>();
    k_scatter<<<gE, 256>>>(ei, eattr);
    k_hinit<<<gN32, 256>>>(x, node_emb);

    for (int l = 0; l < 4; l++) {
        k_etab<<<1, 128>>>(edge_emb, enc_w, enc_b, pre_w, pre_b, l);
        k_pq<<<(NN + 31) / 32, 128>>>(pre_w, l);
        k_stats<<<NB_AGG, 256>>>();
        k_mlp<<<NB_MLP, 256>>>(post_w, post_b, lin_w, lin_b, adl, l);
        k_bnstats<<<148, 256>>>();
        k_bnfin<<<1, 32>>>(bn_g, bn_b, l);
        k_bnapply<<<gN32, 256>>>();
    }
    k_pool<<<gN32, 256>>>(batch);
    k_final<<<GG, 64>>>(mlp_w1, mlp_b1, mlp_w2, mlp_b2, mlp_w3, mlp_b3, out);
}

// round 5
// speedup vs baseline: 2.6860x; 1.0042x over previous
#include <cuda_runtime.h>
#include <math.h>

#define NN 50000
#define EE 800000
#define GG 256
#define NB_AGG 6250   /* ceil(NN/8)    */
#define NB1    49     /* ceil(NN/1024) */
#define NB_MLP 196    /* ceil(NN/256)  */
#define NB_PQ  1563   /* ceil(NN/32)   */

// ---------------- device scratch (no allocations allowed) ----------------
__device__ float g_H[NN * 32];
__device__ float g_O[NN * 32];
__device__ float g_P[NN * 128];
__device__ float g_Q[NN * 128];
__device__ float g_AGG[(size_t)NN * 512];
__device__ float g_Etab[4 * 128];
__device__ int   g_cnt[NN];
__device__ int   g_rowptr[NN + 1];
__device__ int   g_cursor[NN];
__device__ int   g_pack[EE];
__device__ int   g_bsum[64];
__device__ float g_bnacc[64];
__device__ float g_bnAB[64];
__device__ float g_pool[GG * 32];
__device__ int   g_done;

// ---------------- setup kernels ----------------
__global__ void k_zero() {
    int i = blockIdx.x * blockDim.x + threadIdx.x;
    if (i < NN) g_cnt[i] = 0;
    if (i < GG * 32) g_pool[i] = 0.f;
    if (i < 64) g_bnacc[i] = 0.f;
    if (i == 0) g_done = 0;
}

__global__ void k_count(const int* __restrict__ ei) {
    int e = blockIdx.x * blockDim.x + threadIdx.x;
    if (e < EE) atomicAdd(&g_cnt[ei[EE + e]], 1);
}

__global__ void k_scan1() {
    __shared__ int s[1024];
    int t = threadIdx.x;
    int i = blockIdx.x * 1024 + t;
    int v = (i < NN) ? g_cnt[i] : 0;
    s[t] = v;
    __syncthreads();
    for (int off = 1; off < 1024; off <<= 1) {
        int x = (t >= off) ? s[t - off] : 0;
        __syncthreads();
        s[t] += x;
        __syncthreads();
    }
    if (i < NN) g_rowptr[i] = s[t] - v;   // exclusive
    if (t == 1023) g_bsum[blockIdx.x] = s[1023];
}

__global__ void k_scan2() {
    __shared__ int sb[64];
    int t = threadIdx.x;
    if (t < NB1) sb[t] = g_bsum[t];
    __syncthreads();
    if (t == 0) {
        int run = 0;
        for (int b = 0; b < NB1; b++) { int x = sb[b]; sb[b] = run; run += x; }
    }
    __syncthreads();
    if (t < NB1) g_bsum[t] = sb[t];
}

__global__ void k_scan3() {
    int i = blockIdx.x * blockDim.x + threadIdx.x;
    if (i < NN) {
        int v = g_rowptr[i] + g_bsum[i >> 10];
        g_rowptr[i] = v;
        g_cursor[i] = v;
    }
    if (i == 0) g_rowptr[NN] = EE;
}

__global__ void k_scatter(const int* __restrict__ ei, const int* __restrict__ eattr) {
    int e = blockIdx.x * blockDim.x + threadIdx.x;
    if (e >= EE) return;
    int src = ei[e];
    int dst = ei[EE + e];
    int at  = eattr[e];
    int pos = atomicAdd(&g_cursor[dst], 1);
    g_pack[pos] = src | (at << 16);
}

__global__ void k_hinit(const int* __restrict__ x, const float* __restrict__ node_emb) {
    int i = blockIdx.x * blockDim.x + threadIdx.x;
    if (i >= NN * 32) return;
    int n = i >> 5, f = i & 31;
    g_H[i] = node_emb[x[n] * 32 + f];
}

// ---------------- fused per-layer kernels ----------------
// k_pq: (block0: Etab) + (all blocks: BN-apply+relu of prev g_O -> h, P=h@A, Q=h@B)
__global__ void __launch_bounds__(128) k_pq(
    const float* __restrict__ pre_w, const float* __restrict__ pre_b,
    const float* __restrict__ edge_emb, const float* __restrict__ enc_w,
    const float* __restrict__ enc_b, int l) {
    __shared__ float sh[32 * 32];
    int tid = threadIdx.x;
    int t = tid >> 5, o = tid & 31;

    if (blockIdx.x == 0) {
        // Etab: e32 staged in sh[0..127]
        {
            int a = tid >> 5, f = tid & 31;
            float acc = enc_b[l * 32 + f];
            for (int k = 0; k < 50; k++)
                acc += edge_emb[a * 50 + k] * enc_w[(l * 50 + k) * 32 + f];
            sh[a * 32 + f] = acc;
        }
        __syncthreads();
        float ea[4];
#pragma unroll
        for (int a = 0; a < 4; a++) {
            float acc = pre_b[(l * 4 + t) * 32 + o];
            for (int f = 0; f < 32; f++)
                acc += sh[a * 32 + f] * pre_w[((l * 4 + t) * 96 + 64 + f) * 32 + o];
            ea[a] = acc;
        }
        __syncthreads();
#pragma unroll
        for (int a = 0; a < 4; a++) g_Etab[a * 128 + tid] = ea[a];
        __syncthreads();
    }

    const float* base = pre_w + ((size_t)(l * 4 + t) * 96) * 32 + o;
    float wa[32], wb[32];
#pragma unroll
    for (int f = 0; f < 32; f++) {
        wa[f] = base[f * 32];
        wb[f] = base[(f + 32) * 32];
    }
    int n0 = blockIdx.x * 32;
    for (int idx = tid; idx < 1024; idx += 128) {
        int node = idx >> 5, f = idx & 31;
        int n = n0 + node;
        float v = 0.f;
        if (n < NN) {
            if (l == 0) {
                v = g_H[n * 32 + f];
            } else {
                float ov = g_O[n * 32 + f];
                v = fmaxf(ov * g_bnAB[f] + g_bnAB[32 + f], 0.f);
                g_H[n * 32 + f] = v;
            }
        }
        sh[idx] = v;
    }
    __syncthreads();
    for (int node = 0; node < 32; node++) {
        int n = n0 + node;
        if (n >= NN) break;
        float p = 0.f, q = 0.f;
#pragma unroll
        for (int f = 0; f < 32; f++) {
            float hv = sh[node * 32 + f];
            p += hv * wa[f];
            q += hv * wb[f];
        }
        g_P[(size_t)n * 128 + tid] = p;
        g_Q[(size_t)n * 128 + tid] = q;
    }
}

#define ACC4(v)                                                          \
    s.x += (v).x; s.y += (v).y; s.z += (v).z; s.w += (v).w;              \
    sq.x += (v).x * (v).x; sq.y += (v).y * (v).y;                        \
    sq.z += (v).z * (v).z; sq.w += (v).w * (v).w;                        \
    mn.x = fminf(mn.x, (v).x); mn.y = fminf(mn.y, (v).y);                \
    mn.z = fminf(mn.z, (v).z); mn.w = fminf(mn.w, (v).w);                \
    mx.x = fmaxf(mx.x, (v).x); mx.y = fmaxf(mx.y, (v).y);                \
    mx.z = fmaxf(mx.z, (v).z); mx.w = fmaxf(mx.w, (v).w);

// One warp per node: CSR gather + PNA stats -> g_AGG[N][512]
__global__ void __launch_bounds__(256) k_stats() {
    __shared__ float4 sEt[4][32];
    int warp = threadIdx.x >> 5, lane = threadIdx.x & 31;
    int n = blockIdx.x * 8 + warp;
    if (threadIdx.x < 128) {
        int a = threadIdx.x >> 5, L2 = threadIdx.x & 31;
        sEt[a][L2] = ((const float4*)g_Etab)[a * 32 + L2];
    }
    __syncthreads();
    if (n >= NN) return;

    int start = g_rowptr[n], end = g_rowptr[n + 1];
    const float4* Qv = (const float4*)g_Q;
    float4 s  = make_float4(0.f, 0.f, 0.f, 0.f);
    float4 sq = make_float4(0.f, 0.f, 0.f, 0.f);
    float4 mn = make_float4(1e30f, 1e30f, 1e30f, 1e30f);
    float4 mx = make_float4(-1e30f, -1e30f, -1e30f, -1e30f);
    int i = start;
    for (; i + 4 <= end; i += 4) {
        int pk0 = __ldg(&g_pack[i]);
        int pk1 = __ldg(&g_pack[i + 1]);
        int pk2 = __ldg(&g_pack[i + 2]);
        int pk3 = __ldg(&g_pack[i + 3]);
        float4 v0 = Qv[(size_t)(pk0 & 0xFFFF) * 32 + lane];
        float4 v1 = Qv[(size_t)(pk1 & 0xFFFF) * 32 + lane];
        float4 v2 = Qv[(size_t)(pk2 & 0xFFFF) * 32 + lane];
        float4 v3 = Qv[(size_t)(pk3 & 0xFFFF) * 32 + lane];
        float4 e0 = sEt[pk0 >> 16][lane];
        float4 e1 = sEt[pk1 >> 16][lane];
        float4 e2 = sEt[pk2 >> 16][lane];
        float4 e3 = sEt[pk3 >> 16][lane];
        v0.x += e0.x; v0.y += e0.y; v0.z += e0.z; v0.w += e0.w;
        v1.x += e1.x; v1.y += e1.y; v1.z += e1.z; v1.w += e1.w;
        v2.x += e2.x; v2.y += e2.y; v2.z += e2.z; v2.w += e2.w;
        v3.x += e3.x; v3.y += e3.y; v3.z += e3.z; v3.w += e3.w;
        ACC4(v0) ACC4(v1) ACC4(v2) ACC4(v3)
    }
    for (; i < end; i++) {
        int pk = __ldg(&g_pack[i]);
        float4 v = Qv[(size_t)(pk & 0xFFFF) * 32 + lane];
        float4 e = sEt[pk >> 16][lane];
        v.x += e.x; v.y += e.y; v.z += e.z; v.w += e.w;
        ACC4(v)
    }
    int   deg  = end - start;
    float degf = (float)deg;
    float degc = fmaxf(degf, 1.f);
    float inv  = 1.f / degc;
    float4 p = ((const float4*)g_P)[(size_t)n * 32 + lane];

    float pv[4]  = {p.x, p.y, p.z, p.w};
    float sv[4]  = {s.x, s.y, s.z, s.w};
    float qv[4]  = {sq.x, sq.y, sq.z, sq.w};
    float mnv[4] = {mn.x, mn.y, mn.z, mn.w};
    float mxv[4] = {mx.x, mx.y, mx.z, mx.w};
    float4 st0, st1, st2, st3;
    float* o0 = (float*)&st0; float* o1 = (float*)&st1;
    float* o2 = (float*)&st2; float* o3 = (float*)&st3;
#pragma unroll
    for (int k = 0; k < 4; k++) {
        float mean = (degf * pv[k] + sv[k]) * inv;
        float msq  = (degf * pv[k] * pv[k] + 2.f * pv[k] * sv[k] + qv[k]) * inv;
        float var  = fmaxf(msq - mean * mean, 0.f) + 1e-5f;
        o0[k] = mean;
        o1[k] = (deg > 0) ? pv[k] + mnv[k] : 0.f;
        o2[k] = (deg > 0) ? pv[k] + mxv[k] : 0.f;
        o3[k] = sqrtf(var);
    }
    // AGG layout: [n][t*128 + st*32 + o]
    size_t base = (size_t)n * 512 + (size_t)((lane >> 3) * 128 + (lane & 7) * 4);
    *(float4*)&g_AGG[base]       = st0;
    *(float4*)&g_AGG[base + 32]  = st1;
    *(float4*)&g_AGG[base + 64]  = st2;
    *(float4*)&g_AGG[base + 96]  = st3;
}

#define FMA8(acc, av, v0, v1)                                             \
    acc[0] += (av) * (v0).x; acc[1] += (av) * (v0).y;                     \
    acc[2] += (av) * (v0).z; acc[3] += (av) * (v0).w;                     \
    acc[4] += (av) * (v1).x; acc[5] += (av) * (v1).y;                     \
    acc[6] += (av) * (v1).z; acc[7] += (av) * (v1).w;

// Thread per node: fused post-MLP + lin + BN-stats + (last block) BN-finalize.
// BN scratch (65 words) aliased into sW after all sW reads complete: static
// smem stays at exactly 48KB.
__global__ void __launch_bounds__(256) k_mlp(
    const float* __restrict__ post_w, const float* __restrict__ post_b,
    const float* __restrict__ lin_w,  const float* __restrict__ lin_b,
    const float* __restrict__ bn_g,   const float* __restrict__ bn_b,
    const float* __restrict__ adl_p,  int l) {
    __shared__ float sW[12288];   // [t][r(128)][m(3)][c(8)] = 48KB (static max)
    int tid = threadIdx.x;
    const float* pw = post_w + (size_t)l * 4 * 416 * 8;
    for (int idx = tid; idx < 12288; idx += 256) {
        int c  = idx & 7;
        int rm = idx >> 3;
        int m  = rm % 3;
        int tr = rm / 3;
        int r  = tr & 127;
        int t  = tr >> 7;
        sW[idx] = pw[((size_t)t * 416 + 32 + m * 128 + r) * 8 + c];
    }
    __syncthreads();
    int n = blockIdx.x * 256 + tid;
    bool valid = (n < NN);
    int lane = tid & 31;

    float acc[32];
#pragma unroll
    for (int j = 0; j < 32; j++) acc[j] = 0.f;

    if (valid) {
        int deg = g_rowptr[n + 1] - g_rowptr[n];
        float degc = fmaxf((float)deg, 1.f);
        float adl  = __ldg(adl_p);
        float logd = logf(degc + 1.f);
        float amp  = logd / adl;
        float att  = adl / logd;

        float o32[32];
#pragma unroll
        for (int t = 0; t < 4; t++)
#pragma unroll
            for (int c = 0; c < 8; c++)
                o32[t * 8 + c] = __ldg(&post_b[(l * 4 + t) * 8 + c]);

        // h part: rows 0..31 of each tower's post_w (uniform reads, L1-hot)
        {
            const float* hrow = g_H + (size_t)n * 32;
#pragma unroll 8
            for (int f = 0; f < 32; f++) {
                float hv = __ldg(&hrow[f]);
#pragma unroll
                for (int t = 0; t < 4; t++) {
                    const float4* wr = (const float4*)(pw + ((size_t)t * 416 + f) * 8);
                    float4 w0 = __ldg(wr), w1 = __ldg(wr + 1);
                    float* a8 = &o32[t * 8];
                    FMA8(a8, hv, w0, w1);
                }
            }
        }

        // agg part: per tower, 128 rows x 3 matrices from smem (broadcast)
#pragma unroll
        for (int t = 0; t < 4; t++) {
            float y1[8] = {0}, y2[8] = {0}, y3[8] = {0};
            const float* arow = g_AGG + (size_t)n * 512 + t * 128;
            for (int r = 0; r < 128; r += 4) {
                float4 av = __ldg((const float4*)(arow + r));
                float a[4] = {av.x, av.y, av.z, av.w};
#pragma unroll
                for (int rr = 0; rr < 4; rr++) {
                    const float4* wb = (const float4*)&sW[(t * 128 + r + rr) * 24];
                    float4 b0 = wb[0], b1 = wb[1];
                    FMA8(y1, a[rr], b0, b1);
                    float4 c0 = wb[2], c1 = wb[3];
                    FMA8(y2, a[rr], c0, c1);
                    float4 d0 = wb[4], d1 = wb[5];
                    FMA8(y3, a[rr], d0, d1);
                }
            }
#pragma unroll
            for (int c = 0; c < 8; c++)
                o32[t * 8 + c] += y1[c] + amp * y2[c] + att * y3[c];
        }

        // lin
        {
            const float* lb = lin_b + l * 32;
#pragma unroll
            for (int j = 0; j < 8; j++) {
                float4 b = __ldg((const float4*)(lb + j * 4));
                acc[j * 4] = b.x; acc[j * 4 + 1] = b.y; acc[j * 4 + 2] = b.z; acc[j * 4 + 3] = b.w;
            }
            const float* lw = lin_w + l * 1024;
#pragma unroll 8
            for (int c = 0; c < 32; c++) {
                float v = o32[c];
#pragma unroll
                for (int j = 0; j < 8; j++) {
                    float4 w = __ldg((const float4*)(lw + c * 32 + j * 4));
                    acc[j * 4]     += v * w.x;
                    acc[j * 4 + 1] += v * w.y;
                    acc[j * 4 + 2] += v * w.z;
                    acc[j * 4 + 3] += v * w.w;
                }
            }
        }
        float* orow = g_O + (size_t)n * 32;
#pragma unroll
        for (int j = 0; j < 8; j++)
            ((float4*)orow)[j] = make_float4(acc[j * 4], acc[j * 4 + 1], acc[j * 4 + 2], acc[j * 4 + 3]);
    }

    // ---- BN partials; reuse sW[0..64] as scratch (all sW reads are done) ----
    __syncthreads();
    float* sacc  = sW;            // 64 floats: per-channel sum / sumsq
    int*   sflag = (int*)&sW[64]; // last-block flag
    if (tid < 64) sacc[tid] = 0.f;
    __syncthreads();
#pragma unroll
    for (int k = 0; k < 32; k++) {
        float s1 = acc[k];
        float s2 = acc[k] * acc[k];
#pragma unroll
        for (int off = 16; off; off >>= 1) {
            s1 += __shfl_xor_sync(0xffffffffu, s1, off);
            s2 += __shfl_xor_sync(0xffffffffu, s2, off);
        }
        if (lane == 0) {
            atomicAdd(&sacc[k], s1);
            atomicAdd(&sacc[32 + k], s2);
        }
    }
    __syncthreads();
    if (tid < 64) atomicAdd(&g_bnacc[tid], sacc[tid]);
    __threadfence();
    if (tid == 0) *sflag = (atomicAdd(&g_done, 1) == (int)gridDim.x - 1);
    __syncthreads();
    if (*sflag) {
        if (tid < 32) {
            float sum = atomicAdd(&g_bnacc[tid], 0.f);
            float sq  = atomicAdd(&g_bnacc[32 + tid], 0.f);
            float mu  = sum / (float)NN;
            float var = sq / (float)NN - mu * mu;
            float istd = rsqrtf(var + 1e-5f);
            float A = __ldg(&bn_g[l * 32 + tid]) * istd;
            float B = __ldg(&bn_b[l * 32 + tid]) - mu * A;
            g_bnAB[tid]      = A;
            g_bnAB[32 + tid] = B;
            g_bnacc[tid]      = 0.f;
            g_bnacc[32 + tid] = 0.f;
        }
        if (tid == 0) g_done = 0;
    }
}

// ---------------- readout: BN-apply + relu + global_add_pool ----------------
__global__ void k_pool(const int* __restrict__ batch) {
    int i = blockIdx.x * blockDim.x + threadIdx.x;
    if (i >= NN * 32) return;
    int n = i >> 5, c = i & 31;
    float v = fmaxf(g_O[i] * g_bnAB[c] + g_bnAB[32 + c], 0.f);
    atomicAdd(&g_pool[batch[n] * 32 + c], v);
}

__global__ void k_final(const float* __restrict__ w1, const float* __restrict__ b1,
                        const float* __restrict__ w2, const float* __restrict__ b2,
                        const float* __restrict__ w3, const float* __restrict__ b3,
                        float* __restrict__ out) {
    __shared__ float sg[32], s1[50], s2[25];
    int g = blockIdx.x, t = threadIdx.x;
    if (t < 32) sg[t] = g_pool[g * 32 + t];
    __syncthreads();
    if (t < 50) {
        float a = b1[t];
        for (int c = 0; c < 32; c++) a += sg[c] * w1[c * 50 + t];
        s1[t] = fmaxf(a, 0.f);
    }
    __syncthreads();
    if (t < 25) {
        float a = b2[t];
        for (int j = 0; j < 50; j++) a += s1[j] * w2[j * 25 + t];
        s2[t] = fmaxf(a, 0.f);
    }
    __syncthreads();
    if (t == 0) {
        float a = b3[0];
        for (int k = 0; k < 25; k++) a += s2[k] * w3[k];
        out[g] = a;
    }
}

// ---------------- launch ----------------
extern "C" void kernel_launch(void* const* d_in, const int* in_sizes, int n_in,
                              void* d_out, int out_size) {
    const int*   x        = (const int*)d_in[0];
    const int*   ei       = (const int*)d_in[1];
    const int*   eattr    = (const int*)d_in[2];
    const int*   batch    = (const int*)d_in[3];
    const float* node_emb = (const float*)d_in[4];
    const float* edge_emb = (const float*)d_in[5];
    const float* enc_w    = (const float*)d_in[6];
    const float* enc_b    = (const float*)d_in[7];
    const float* pre_w    = (const float*)d_in[8];
    const float* pre_b    = (const float*)d_in[9];
    const float* post_w   = (const float*)d_in[10];
    const float* post_b   = (const float*)d_in[11];
    const float* lin_w    = (const float*)d_in[12];
    const float* lin_b    = (const float*)d_in[13];
    const float* bn_g     = (const float*)d_in[14];
    const float* bn_b     = (const float*)d_in[15];
    const float* mlp_w1   = (const float*)d_in[16];
    const float* mlp_b1   = (const float*)d_in[17];
    const float* mlp_w2   = (const float*)d_in[18];
    const float* mlp_b2   = (const float*)d_in[19];
    const float* mlp_w3   = (const float*)d_in[20];
    const float* mlp_b3   = (const float*)d_in[21];
    const float* adl      = (const float*)d_in[22];
    float* out = (float*)d_out;

    int gN   = (NN + 255) / 256;
    int gE   = (EE + 255) / 256;
    int gN32 = (NN * 32 + 255) / 256;

    k_zero<<<gN, 256>>>();
    k_count<<<gE, 256>>>(ei);
    k_scan1<<<NB1, 1024>>>();
    k_scan2<<<1, 64>>>();
    k_scan3<<<gN, 256>>>();
    k_scatter<<<gE, 256>>>(ei, eattr);
    k_hinit<<<gN32, 256>>>(x, node_emb);

    for (int l = 0; l < 4; l++) {
        k_pq<<<NB_PQ, 128>>>(pre_w, pre_b, edge_emb, enc_w, enc_b, l);
        k_stats<<<NB_AGG, 256>>>();
        k_mlp<<<NB_MLP, 256>>>(post_w, post_b, lin_w, lin_b, bn_g, bn_b, adl, l);
    }
    k_pool<<<gN32, 256>>>(batch);
    k_final<<<GG, 64>>>(mlp_w1, mlp_b1, mlp_w2, mlp_b2, mlp_w3, mlp_b3, out);
}

// round 6
// speedup vs baseline: 2.7394x; 1.0198x over previous
#include <cuda_runtime.h>
#include <math.h>

#define NN 50000
#define EE 800000
#define GG 256
#define NB_AGG 6250   /* ceil(NN/8)    */
#define NB1    49     /* ceil(NN/1024) */
#define NB_MLP 196    /* ceil(NN/256)  */
#define NB_PQ  1563   /* ceil(NN/32)   */

typedef unsigned long long u64;

// ---- packed f32x2 helpers (SASS FFMA2 path, PTX-only per SASS_QUICKREF) ----
__device__ __forceinline__ u64 pk2(float lo, float hi) {
    u64 r; asm("mov.b64 %0, {%1, %2};" : "=l"(r) : "f"(lo), "f"(hi)); return r;
}
__device__ __forceinline__ void upk2(u64 v, float& lo, float& hi) {
    asm("mov.b64 {%0, %1}, %2;" : "=f"(lo), "=f"(hi) : "l"(v));
}
__device__ __forceinline__ void fma2(u64& d, u64 a, u64 b) {
    asm("fma.rn.f32x2 %0, %1, %2, %0;" : "+l"(d) : "l"(a), "l"(b));
}
__device__ __forceinline__ void add2(u64& d, u64 a) {
    asm("add.rn.f32x2 %0, %1, %0;" : "+l"(d) : "l"(a));
}

// ---------------- device scratch (no allocations allowed) ----------------
__device__ float g_H[NN * 32];
__device__ float g_O[NN * 32];
__device__ float g_P[NN * 128];
__device__ float g_Q[NN * 128];
__device__ float g_AGG[(size_t)NN * 512];
__device__ float g_Etab[4 * 128];
__device__ int   g_cnt[NN];          // statically zero; self-restored by k_scan
__device__ int   g_rowptr[NN + 1];
__device__ int   g_cursor[NN];
__device__ int   g_pack[EE];
__device__ float g_bnacc[64];        // statically zero; self-restored by k_mlp
__device__ float g_bnAB[64];
__device__ float g_pool[GG * 32];    // zeroed by k_scan each run
__device__ int   g_done;             // statically zero; self-restored by k_mlp

// ---------------- setup kernels ----------------
__global__ void k_hinit(const int* __restrict__ x, const float* __restrict__ node_emb) {
    int i = blockIdx.x * blockDim.x + threadIdx.x;
    if (i >= NN * 32) return;
    int n = i >> 5, f = i & 31;
    g_H[i] = node_emb[x[n] * 32 + f];
}

__global__ void k_count(const int* __restrict__ ei) {
    int e = blockIdx.x * blockDim.x + threadIdx.x;
    if (e < EE) atomicAdd(&g_cnt[ei[EE + e]], 1);
}

// single-block shuffle scan over 49 chunks; zeroes cnt (for next replay) + pool
__global__ void __launch_bounds__(1024) k_scan() {
    __shared__ int swarp[32];
    __shared__ int s_carry;
    int t = threadIdx.x, lane = t & 31, wid = t >> 5;
    if (t == 0) s_carry = 0;
    for (int i = t; i < GG * 32; i += 1024) g_pool[i] = 0.f;
    __syncthreads();
    for (int chunk = 0; chunk < NB1; chunk++) {
        int i = chunk * 1024 + t;
        int v = (i < NN) ? g_cnt[i] : 0;
        if (i < NN) g_cnt[i] = 0;                    // restore for next replay
        int x = v;
#pragma unroll
        for (int off = 1; off < 32; off <<= 1) {
            int y = __shfl_up_sync(0xffffffffu, x, off);
            if (lane >= off) x += y;
        }
        if (lane == 31) swarp[wid] = x;
        __syncthreads();
        if (wid == 0) {
            int w = swarp[lane];
#pragma unroll
            for (int off = 1; off < 32; off <<= 1) {
                int y = __shfl_up_sync(0xffffffffu, w, off);
                if (lane >= off) w += y;
            }
            swarp[lane] = w;
        }
        __syncthreads();
        int excl = s_carry + (wid ? swarp[wid - 1] : 0) + x - v;
        if (i < NN) { g_rowptr[i] = excl; g_cursor[i] = excl; }
        __syncthreads();
        if (t == 1023) s_carry += swarp[31];
        __syncthreads();
    }
    if (t == 0) g_rowptr[NN] = EE;
}

__global__ void k_scatter(const int* __restrict__ ei, const int* __restrict__ eattr) {
    int e = blockIdx.x * blockDim.x + threadIdx.x;
    if (e >= EE) return;
    int src = ei[e];
    int dst = ei[EE + e];
    int at  = eattr[e];
    int pos = atomicAdd(&g_cursor[dst], 1);
    g_pack[pos] = src | (at << 16);
}

// ---------------- fused per-layer kernels ----------------
// k_pq: (block0: Etab) + (all blocks: BN-apply+relu of prev g_O -> h, P=h@A, Q=h@B)
__global__ void __launch_bounds__(128) k_pq(
    const float* __restrict__ pre_w, const float* __restrict__ pre_b,
    const float* __restrict__ edge_emb, const float* __restrict__ enc_w,
    const float* __restrict__ enc_b, int l) {
    __shared__ float sh[32 * 32];
    int tid = threadIdx.x;
    int t = tid >> 5, o = tid & 31;

    if (blockIdx.x == 0) {
        {
            int a = tid >> 5, f = tid & 31;
            float acc = enc_b[l * 32 + f];
            for (int k = 0; k < 50; k++)
                acc += edge_emb[a * 50 + k] * enc_w[(l * 50 + k) * 32 + f];
            sh[a * 32 + f] = acc;
        }
        __syncthreads();
        float ea[4];
#pragma unroll
        for (int a = 0; a < 4; a++) {
            float acc = pre_b[(l * 4 + t) * 32 + o];
            for (int f = 0; f < 32; f++)
                acc += sh[a * 32 + f] * pre_w[((l * 4 + t) * 96 + 64 + f) * 32 + o];
            ea[a] = acc;
        }
        __syncthreads();
#pragma unroll
        for (int a = 0; a < 4; a++) g_Etab[a * 128 + tid] = ea[a];
        __syncthreads();
    }

    const float* base = pre_w + ((size_t)(l * 4 + t) * 96) * 32 + o;
    float wa[32], wb[32];
#pragma unroll
    for (int f = 0; f < 32; f++) {
        wa[f] = base[f * 32];
        wb[f] = base[(f + 32) * 32];
    }
    int n0 = blockIdx.x * 32;
    for (int idx = tid; idx < 1024; idx += 128) {
        int node = idx >> 5, f = idx & 31;
        int n = n0 + node;
        float v = 0.f;
        if (n < NN) {
            if (l == 0) {
                v = g_H[n * 32 + f];
            } else {
                float ov = g_O[n * 32 + f];
                v = fmaxf(ov * g_bnAB[f] + g_bnAB[32 + f], 0.f);
                g_H[n * 32 + f] = v;
            }
        }
        sh[idx] = v;
    }
    __syncthreads();
    for (int node = 0; node < 32; node++) {
        int n = n0 + node;
        if (n >= NN) break;
        float p = 0.f, q = 0.f;
#pragma unroll
        for (int f = 0; f < 32; f++) {
            float hv = sh[node * 32 + f];
            p += hv * wa[f];
            q += hv * wb[f];
        }
        g_P[(size_t)n * 128 + tid] = p;
        g_Q[(size_t)n * 128 + tid] = q;
    }
}

// packed accumulate of one edge value pair-set
#define ACCP(q, e)                                                        \
    {                                                                     \
        u64 va = (q).x, vb = (q).y;                                       \
        add2(va, (e).x); add2(vb, (e).y);                                 \
        add2(s0, va); add2(s1, vb);                                       \
        fma2(sq0, va, va); fma2(sq1, vb, vb);                             \
        float x0, x1, x2, x3;                                             \
        upk2(va, x0, x1); upk2(vb, x2, x3);                               \
        mnv[0] = fminf(mnv[0], x0); mnv[1] = fminf(mnv[1], x1);           \
        mnv[2] = fminf(mnv[2], x2); mnv[3] = fminf(mnv[3], x3);           \
        mxv[0] = fmaxf(mxv[0], x0); mxv[1] = fmaxf(mxv[1], x1);           \
        mxv[2] = fmaxf(mxv[2], x2); mxv[3] = fmaxf(mxv[3], x3);           \
    }

// One warp per node: CSR gather + PNA stats -> g_AGG[N][512]
__global__ void __launch_bounds__(256) k_stats() {
    __shared__ ulonglong2 sEt[4][32];
    int warp = threadIdx.x >> 5, lane = threadIdx.x & 31;
    int n = blockIdx.x * 8 + warp;
    if (threadIdx.x < 128) {
        int a = threadIdx.x >> 5, L2 = threadIdx.x & 31;
        sEt[a][L2] = ((const ulonglong2*)g_Etab)[a * 32 + L2];
    }
    __syncthreads();
    if (n >= NN) return;

    int start = g_rowptr[n], end = g_rowptr[n + 1];
    const ulonglong2* Qv = (const ulonglong2*)g_Q;
    u64 s0 = 0, s1 = 0, sq0 = 0, sq1 = 0;       // (0.f,0.f) bit pattern == 0
    float mnv[4] = {1e30f, 1e30f, 1e30f, 1e30f};
    float mxv[4] = {-1e30f, -1e30f, -1e30f, -1e30f};
    int i = start;
    for (; i + 4 <= end; i += 4) {
        int pk0 = __ldg(&g_pack[i]);
        int pk1 = __ldg(&g_pack[i + 1]);
        int pk2_ = __ldg(&g_pack[i + 2]);
        int pk3 = __ldg(&g_pack[i + 3]);
        ulonglong2 q0 = __ldg(&Qv[(size_t)(pk0 & 0xFFFF) * 32 + lane]);
        ulonglong2 q1 = __ldg(&Qv[(size_t)(pk1 & 0xFFFF) * 32 + lane]);
        ulonglong2 q2 = __ldg(&Qv[(size_t)(pk2_ & 0xFFFF) * 32 + lane]);
        ulonglong2 q3 = __ldg(&Qv[(size_t)(pk3 & 0xFFFF) * 32 + lane]);
        ulonglong2 e0 = sEt[pk0 >> 16][lane];
        ulonglong2 e1 = sEt[pk1 >> 16][lane];
        ulonglong2 e2 = sEt[pk2_ >> 16][lane];
        ulonglong2 e3 = sEt[pk3 >> 16][lane];
        ACCP(q0, e0) ACCP(q1, e1) ACCP(q2, e2) ACCP(q3, e3)
    }
    for (; i < end; i++) {
        int pk = __ldg(&g_pack[i]);
        ulonglong2 q = __ldg(&Qv[(size_t)(pk & 0xFFFF) * 32 + lane]);
        ulonglong2 e = sEt[pk >> 16][lane];
        ACCP(q, e)
    }
    int   deg  = end - start;
    float degf = (float)deg;
    float degc = fmaxf(degf, 1.f);
    float inv  = 1.f / degc;
    float4 p = ((const float4*)g_P)[(size_t)n * 32 + lane];

    float pv[4] = {p.x, p.y, p.z, p.w};
    float sv[4], qv[4];
    upk2(s0, sv[0], sv[1]); upk2(s1, sv[2], sv[3]);
    upk2(sq0, qv[0], qv[1]); upk2(sq1, qv[2], qv[3]);
    float4 st0, st1, st2, st3;
    float* o0 = (float*)&st0; float* o1 = (float*)&st1;
    float* o2 = (float*)&st2; float* o3 = (float*)&st3;
#pragma unroll
    for (int k = 0; k < 4; k++) {
        float mean = (degf * pv[k] + sv[k]) * inv;
        float msq  = (degf * pv[k] * pv[k] + 2.f * pv[k] * sv[k] + qv[k]) * inv;
        float var  = fmaxf(msq - mean * mean, 0.f) + 1e-5f;
        o0[k] = mean;
        o1[k] = (deg > 0) ? pv[k] + mnv[k] : 0.f;
        o2[k] = (deg > 0) ? pv[k] + mxv[k] : 0.f;
        o3[k] = sqrtf(var);
    }
    size_t base = (size_t)n * 512 + (size_t)((lane >> 3) * 128 + (lane & 7) * 4);
    *(float4*)&g_AGG[base]       = st0;
    *(float4*)&g_AGG[base + 32]  = st1;
    *(float4*)&g_AGG[base + 64]  = st2;
    *(float4*)&g_AGG[base + 96]  = st3;
}

// Thread per node: fused post-MLP + lin + BN-stats + (last block) BN-finalize.
// All heavy FMA blocks use packed f32x2; weights loaded directly as u64.
__global__ void __launch_bounds__(256) k_mlp(
    const float* __restrict__ post_w, const float* __restrict__ post_b,
    const float* __restrict__ lin_w,  const float* __restrict__ lin_b,
    const float* __restrict__ bn_g,   const float* __restrict__ bn_b,
    const float* __restrict__ adl_p,  int l) {
    __shared__ float sW[12288];   // [t][r(128)][m(3)][c(8)] = 48KB (static max)
    int tid = threadIdx.x;
    const float* pw = post_w + (size_t)l * 4 * 416 * 8;
    for (int idx = tid; idx < 12288; idx += 256) {
        int c  = idx & 7;
        int rm = idx >> 3;
        int m  = rm % 3;
        int tr = rm / 3;
        int r  = tr & 127;
        int t  = tr >> 7;
        sW[idx] = pw[((size_t)t * 416 + 32 + m * 128 + r) * 8 + c];
    }
    __syncthreads();
    int n = blockIdx.x * 256 + tid;
    bool valid = (n < NN);
    int lane = tid & 31;

    u64 acc[16];
#pragma unroll
    for (int j = 0; j < 16; j++) acc[j] = 0ull;

    if (valid) {
        int deg = g_rowptr[n + 1] - g_rowptr[n];
        float degc = fmaxf((float)deg, 1.f);
        float adl  = __ldg(adl_p);
        float logd = logf(degc + 1.f);
        float amp  = logd / adl;
        float att  = adl / logd;

        u64 ob[16];
#pragma unroll
        for (int t = 0; t < 4; t++)
#pragma unroll
            for (int c = 0; c < 4; c++)
                ob[t * 4 + c] = __ldg((const u64*)&post_b[(l * 4 + t) * 8 + c * 2]);

        // h part: rows 0..31 of each tower's post_w (uniform u64 reads, L1-hot)
        {
            const float* hrow = g_H + (size_t)n * 32;
#pragma unroll 8
            for (int f = 0; f < 32; f++) {
                float hv = __ldg(&hrow[f]);
                u64 h2 = pk2(hv, hv);
#pragma unroll
                for (int t = 0; t < 4; t++) {
                    const u64* wr = (const u64*)(pw + ((size_t)t * 416 + f) * 8);
#pragma unroll
                    for (int c = 0; c < 4; c++) fma2(ob[t * 4 + c], h2, __ldg(&wr[c]));
                }
            }
        }

        // agg part: per tower, 128 rows x 3 matrices from smem (u64 broadcast)
#pragma unroll
        for (int t = 0; t < 4; t++) {
            u64 y1[4] = {0, 0, 0, 0}, y2[4] = {0, 0, 0, 0}, y3[4] = {0, 0, 0, 0};
            const float* arow = g_AGG + (size_t)n * 512 + t * 128;
            for (int r = 0; r < 128; r += 4) {
                float4 av = __ldg((const float4*)(arow + r));
                float a[4] = {av.x, av.y, av.z, av.w};
#pragma unroll
                for (int rr = 0; rr < 4; rr++) {
                    u64 a2 = pk2(a[rr], a[rr]);
                    const u64* wb = (const u64*)&sW[(t * 128 + r + rr) * 24];
#pragma unroll
                    for (int c = 0; c < 4; c++) {
                        fma2(y1[c], a2, wb[c]);
                        fma2(y2[c], a2, wb[4 + c]);
                        fma2(y3[c], a2, wb[8 + c]);
                    }
                }
            }
            u64 amp2 = pk2(amp, amp), att2 = pk2(att, att);
#pragma unroll
            for (int c = 0; c < 4; c++) {
                fma2(y1[c], amp2, y2[c]);
                fma2(y1[c], att2, y3[c]);
                add2(ob[t * 4 + c], y1[c]);
            }
        }

        // lin (packed): acc = lin_b + o32 @ lin_w
        float o32[32];
#pragma unroll
        for (int j = 0; j < 16; j++) upk2(ob[j], o32[j * 2], o32[j * 2 + 1]);
        const float* lb = lin_b + l * 32;
#pragma unroll
        for (int j = 0; j < 16; j++) acc[j] = __ldg((const u64*)&lb[j * 2]);
        const float* lw = lin_w + l * 1024;
#pragma unroll 8
        for (int c = 0; c < 32; c++) {
            u64 v2 = pk2(o32[c], o32[c]);
            const u64* wr = (const u64*)&lw[c * 32];
#pragma unroll
            for (int j = 0; j < 16; j++) fma2(acc[j], v2, __ldg(&wr[j]));
        }
        u64* orow = (u64*)(g_O + (size_t)n * 32);
#pragma unroll
        for (int j = 0; j < 16; j++) orow[j] = acc[j];
    }

    // ---- BN partials; reuse sW[0..64] as scratch (all sW reads done) ----
    __syncthreads();
    float* sacc  = sW;
    int*   sflag = (int*)&sW[64];
    if (tid < 64) sacc[tid] = 0.f;
    __syncthreads();
#pragma unroll
    for (int j = 0; j < 16; j++) {
        float a0, a1; upk2(acc[j], a0, a1);
        float s1 = a0, s2 = a0 * a0, s3 = a1, s4 = a1 * a1;
#pragma unroll
        for (int off = 16; off; off >>= 1) {
            s1 += __shfl_xor_sync(0xffffffffu, s1, off);
            s2 += __shfl_xor_sync(0xffffffffu, s2, off);
            s3 += __shfl_xor_sync(0xffffffffu, s3, off);
            s4 += __shfl_xor_sync(0xffffffffu, s4, off);
        }
        if (lane == 0) {
            atomicAdd(&sacc[2 * j], s1);
            atomicAdd(&sacc[32 + 2 * j], s2);
            atomicAdd(&sacc[2 * j + 1], s3);
            atomicAdd(&sacc[32 + 2 * j + 1], s4);
        }
    }
    __syncthreads();
    if (tid < 64) atomicAdd(&g_bnacc[tid], sacc[tid]);
    __threadfence();
    if (tid == 0) *sflag = (atomicAdd(&g_done, 1) == (int)gridDim.x - 1);
    __syncthreads();
    if (*sflag) {
        if (tid < 32) {
            float sum = atomicAdd(&g_bnacc[tid], 0.f);
            float sq  = atomicAdd(&g_bnacc[32 + tid], 0.f);
            float mu  = sum / (float)NN;
            float var = sq / (float)NN - mu * mu;
            float istd = rsqrtf(var + 1e-5f);
            float A = __ldg(&bn_g[l * 32 + tid]) * istd;
            float B = __ldg(&bn_b[l * 32 + tid]) - mu * A;
            g_bnAB[tid]      = A;
            g_bnAB[32 + tid] = B;
            g_bnacc[tid]      = 0.f;
            g_bnacc[32 + tid] = 0.f;
        }
        if (tid == 0) g_done = 0;
    }
}

// ---------------- readout: BN-apply + relu + global_add_pool ----------------
__global__ void k_pool(const int* __restrict__ batch) {
    int i = blockIdx.x * blockDim.x + threadIdx.x;
    if (i >= NN * 32) return;
    int n = i >> 5, c = i & 31;
    float v = fmaxf(g_O[i] * g_bnAB[c] + g_bnAB[32 + c], 0.f);
    atomicAdd(&g_pool[batch[n] * 32 + c], v);
}

__global__ void k_final(const float* __restrict__ w1, const float* __restrict__ b1,
                        const float* __restrict__ w2, const float* __restrict__ b2,
                        const float* __restrict__ w3, const float* __restrict__ b3,
                        float* __restrict__ out) {
    __shared__ float sg[32], s1[50], s2[25];
    int g = blockIdx.x, t = threadIdx.x;
    if (t < 32) sg[t] = g_pool[g * 32 + t];
    __syncthreads();
    if (t < 50) {
        float a = b1[t];
        for (int c = 0; c < 32; c++) a += sg[c] * w1[c * 50 + t];
        s1[t] = fmaxf(a, 0.f);
    }
    __syncthreads();
    if (t < 25) {
        float a = b2[t];
        for (int j = 0; j < 50; j++) a += s1[j] * w2[j * 25 + t];
        s2[t] = fmaxf(a, 0.f);
    }
    __syncthreads();
    if (t == 0) {
        float a = b3[0];
        for (int k = 0; k < 25; k++) a += s2[k] * w3[k];
        out[g] = a;
    }
}

// ---------------- launch ----------------
extern "C" void kernel_launch(void* const* d_in, const int* in_sizes, int n_in,
                              void* d_out, int out_size) {
    const int*   x        = (const int*)d_in[0];
    const int*   ei       = (const int*)d_in[1];
    const int*   eattr    = (const int*)d_in[2];
    const int*   batch    = (const int*)d_in[3];
    const float* node_emb = (const float*)d_in[4];
    const float* edge_emb = (const float*)d_in[5];
    const float* enc_w    = (const float*)d_in[6];
    const float* enc_b    = (const float*)d_in[7];
    const float* pre_w    = (const float*)d_in[8];
    const float* pre_b    = (const float*)d_in[9];
    const float* post_w   = (const float*)d_in[10];
    const float* post_b   = (const float*)d_in[11];
    const float* lin_w    = (const float*)d_in[12];
    const float* lin_b    = (const float*)d_in[13];
    const float* bn_g     = (const float*)d_in[14];
    const float* bn_b     = (const float*)d_in[15];
    const float* mlp_w1   = (const float*)d_in[16];
    const float* mlp_b1   = (const float*)d_in[17];
    const float* mlp_w2   = (const float*)d_in[18];
    const float* mlp_b2   = (const float*)d_in[19];
    const float* mlp_w3   = (const float*)d_in[20];
    const float* mlp_b3   = (const float*)d_in[21];
    const float* adl      = (const float*)d_in[22];
    float* out = (float*)d_out;

    int gE   = (EE + 255) / 256;
    int gN32 = (NN * 32 + 255) / 256;

    k_hinit<<<gN32, 256>>>(x, node_emb);
    k_count<<<gE, 256>>>(ei);
    k_scan<<<1, 1024>>>();
    k_scatter<<<gE, 256>>>(ei, eattr);

    for (int l = 0; l < 4; l++) {
        k_pq<<<NB_PQ, 128>>>(pre_w, pre_b, edge_emb, enc_w, enc_b, l);
        k_stats<<<NB_AGG, 256>>>();
        k_mlp<<<NB_MLP, 256>>>(post_w, post_b, lin_w, lin_b, bn_g, bn_b, adl, l);
    }
    k_pool<<<gN32, 256>>>(batch);
    k_final<<<GG, 64>>>(mlp_w1, mlp_b1, mlp_w2, mlp_b2, mlp_w3, mlp_b3, out);
}